// round 15
// baseline (speedup 1.0000x reference)
#include <cuda_runtime.h>
#include <cuda_bf16.h>

// GATConv (PyG default, add self-loops), fp32.  N=100000, D=128, H=8, C=16,
// E=800000, Etot=900000.
//
// R12: parallel dtype-detect (was a serial 1-thread load chain, ~40-70us
// hidden); GEMM inner loop loads Xs as float2 along k (halves Xs smem
// wavefronts; R11 profile showed L1=72.6% > fma=50.1% => smem-bound).

#define NN 100000
#define DD 128
#define HH 8
#define CC 16
#define EE 800000
#define ETOT 900000          // EE + NN
#define NB  ((NN + 255) / 256)   // 391 scan blocks

// ---------------- device scratch ----------------------------------------------
__device__ float g_h[NN * DD];          // 51.2 MB
__device__ float g_as[NN * HH];
__device__ float g_ad[NN * HH];
__device__ int   g_cnt[NN];
__device__ int   g_loc[NN];
__device__ int   g_bsum[NB];
__device__ int   g_off[NN + 1];
__device__ int   g_cur[NN];
__device__ int   g_srcList[ETOT];
__device__ int   g_eidList[ETOT];
__device__ int   g_is64;

// ---------------- dtype detect (parallel: 32 lanes x 8 loads + ballot) ---------
__global__ void k_detect(const void* __restrict__ ei) {
    int lane = threadIdx.x;
    const long long* p64 = (const long long*)ei;
    bool ok = true;
#pragma unroll
    for (int i = 0; i < 8; i++) {
        long long v = p64[lane + i * 32];
        if (v < 0 || v >= NN) ok = false;
    }
    unsigned m = __ballot_sync(0xFFFFFFFFu, ok);
    if (lane == 0) g_is64 = (m == 0xFFFFFFFFu) ? 1 : 0;
}

// ---------------- edge decode (dtype-aware) ------------------------------------
__device__ __forceinline__ bool edge_src_dst(const void* __restrict__ ei, int e,
                                             int& src, int& dst) {
    if (e >= EE) { src = dst = e - EE; return true; }   // self-loop
    if (g_is64) {
        src = (int)((const long long*)ei)[e];
        dst = (int)((const long long*)ei)[EE + e];
    } else {
        src = ((const int*)ei)[e];
        dst = ((const int*)ei)[EE + e];
    }
    return (unsigned)src < NN && (unsigned)dst < NN;
}

// ---------------- CSR build -----------------------------------------------------
__global__ void k_cnt_init() {
    int i = blockIdx.x * blockDim.x + threadIdx.x;
    if (i < NN) g_cnt[i] = 1;
}

__global__ void k_hist(const void* __restrict__ ei) {
    int e = blockIdx.x * blockDim.x + threadIdx.x;
    if (e >= EE) return;
    int src, dst;
    if (!edge_src_dst(ei, e, src, dst)) return;
    atomicAdd(&g_cnt[dst], 1);
}

__global__ void k_scan1() {
    __shared__ int s[256];
    int t = threadIdx.x;
    int i = blockIdx.x * 256 + t;
    int v = (i < NN) ? g_cnt[i] : 0;
    s[t] = v;
    __syncthreads();
#pragma unroll
    for (int d = 1; d < 256; d <<= 1) {
        int add = (t >= d) ? s[t - d] : 0;
        __syncthreads();
        s[t] += add;
        __syncthreads();
    }
    if (i < NN) g_loc[i] = s[t] - v;
    if (t == 255) g_bsum[blockIdx.x] = s[255];
}

__global__ void k_scan2() {
    __shared__ int s[512];
    int t = threadIdx.x;
    int v = (t < NB) ? g_bsum[t] : 0;
    s[t] = v;
    __syncthreads();
#pragma unroll
    for (int d = 1; d < 512; d <<= 1) {
        int add = (t >= d) ? s[t - d] : 0;
        __syncthreads();
        s[t] += add;
        __syncthreads();
    }
    if (t < NB) g_bsum[t] = s[t] - v;
}

__global__ void k_scan3() {
    int i = blockIdx.x * blockDim.x + threadIdx.x;
    if (i < NN) {
        int o = g_loc[i] + g_bsum[i >> 8];
        g_off[i] = o;
        g_cur[i] = o;
    }
    if (i == 0) g_off[NN] = ETOT;
}

__global__ void k_fill(const void* __restrict__ ei) {
    int e = blockIdx.x * blockDim.x + threadIdx.x;
    if (e >= ETOT) return;
    int src, dst;
    if (!edge_src_dst(ei, e, src, dst)) return;
    int pos = atomicAdd(&g_cur[dst], 1);
    g_srcList[pos] = src;
    g_eidList[pos] = e;
}

// ---------------- f32x2 helpers -------------------------------------------------
__device__ __forceinline__ unsigned long long pack2(float lo, float hi) {
    unsigned long long r;
    asm("mov.b64 %0, {%1, %2};" : "=l"(r) : "f"(lo), "f"(hi));
    return r;
}
__device__ __forceinline__ void unpack2(unsigned long long p, float& lo, float& hi) {
    asm("mov.b64 {%0, %1}, %2;" : "=f"(lo), "=f"(hi) : "l"(p));
}
__device__ __forceinline__ void fma2(unsigned long long& d, unsigned long long a,
                                     unsigned long long b) {
    asm("fma.rn.f32x2 %0, %1, %2, %0;" : "+l"(d) : "l"(a), "l"(b));
}

// ---------------- cp.async helpers ----------------------------------------------
__device__ __forceinline__ void cp16(void* smem_dst, const void* gsrc, int bytes) {
    unsigned int d = (unsigned int)__cvta_generic_to_shared(smem_dst);
    asm volatile("cp.async.ca.shared.global [%0], [%1], 16, %2;"
                 :: "r"(d), "l"(gsrc), "r"(bytes));
}
__device__ __forceinline__ void cp_commit() {
    asm volatile("cp.async.commit_group;");
}
template <int Ngroups>
__device__ __forceinline__ void cp_wait() {
    asm volatile("cp.async.wait_group %0;" :: "n"(Ngroups));
}

// ---------------- GEMM: h = x @ W, fused attn dots -----------------------------
// 128x128 tile, 256 threads, 8x8 f32x2 micro-tile, cp.async double buffer, KC=16.
// Xs read as float2 along k (2 k-steps per a-load) to halve Xs smem wavefronts.
#define KC 16
#define XPAD 20   // floats per Xs row: 80 bytes, 16B-aligned for cp.async

__global__ __launch_bounds__(256, 2) void k_gemm(const float* __restrict__ x,
                                                 const float* __restrict__ W,
                                                 const float* __restrict__ att_src,
                                                 const float* __restrict__ att_dst) {
    __shared__ float Xs[2][128][XPAD];
    __shared__ float Ws[2][KC][128];
    const int tid = threadIdx.x;
    const int tx = tid & 15;
    const int ty = tid >> 4;
    const int rowBase = blockIdx.x * 128;

    unsigned long long acc[8][4];
#pragma unroll
    for (int i = 0; i < 8; i++)
#pragma unroll
        for (int j = 0; j < 4; j++) acc[i][j] = 0ull;

    auto stage = [&](int k0, int buf) {
#pragma unroll
        for (int i = tid; i < 512; i += 256) {
            int r = i >> 2;
            int k4 = i & 3;
            int gr = rowBase + r;
            cp16(&Xs[buf][r][k4 * 4],
                 x + (size_t)(gr < NN ? gr : 0) * DD + k0 + k4 * 4,
                 gr < NN ? 16 : 0);
        }
#pragma unroll
        for (int i = tid; i < 512; i += 256) {
            int kk = i >> 5;
            int c4 = i & 31;
            cp16(&Ws[buf][kk][c4 * 4], W + (size_t)(k0 + kk) * DD + c4 * 4, 16);
        }
        cp_commit();
    };

    stage(0, 0);

#pragma unroll
    for (int it = 0; it < 8; it++) {
        if (it < 7) stage((it + 1) * KC, (it + 1) & 1);
        if (it < 7) cp_wait<1>(); else cp_wait<0>();
        __syncthreads();
        const int b = it & 1;
#pragma unroll
        for (int g = 0; g < KC / 2; g++) {
            float2 a2[8];
#pragma unroll
            for (int i = 0; i < 8; i++)
                a2[i] = *(const float2*)(&Xs[b][ty * 8 + i][g * 2]);
#pragma unroll
            for (int kq = 0; kq < 2; kq++) {
                const int kk = g * 2 + kq;
                float4 b0 = *(const float4*)(&Ws[b][kk][tx * 8]);
                float4 b1 = *(const float4*)(&Ws[b][kk][tx * 8 + 4]);
                unsigned long long bp[4];
                bp[0] = pack2(b0.x, b0.y);
                bp[1] = pack2(b0.z, b0.w);
                bp[2] = pack2(b1.x, b1.y);
                bp[3] = pack2(b1.z, b1.w);
#pragma unroll
                for (int i = 0; i < 8; i++) {
                    float a = kq ? a2[i].y : a2[i].x;
                    unsigned long long ap = pack2(a, a);
#pragma unroll
                    for (int j = 0; j < 4; j++) fma2(acc[i][j], ap, bp[j]);
                }
            }
        }
        __syncthreads();
    }

    // attn vectors for this thread's 8 columns (all in head tx/2)
    const int head = tx >> 1;
    const int cbase = head * CC + (tx & 1) * 8;
    float4 as0 = *(const float4*)(att_src + cbase);
    float4 as1 = *(const float4*)(att_src + cbase + 4);
    float4 ad0 = *(const float4*)(att_dst + cbase);
    float4 ad1 = *(const float4*)(att_dst + cbase + 4);
    float av[8] = {as0.x, as0.y, as0.z, as0.w, as1.x, as1.y, as1.z, as1.w};
    float dv[8] = {ad0.x, ad0.y, ad0.z, ad0.w, ad1.x, ad1.y, ad1.z, ad1.w};

#pragma unroll
    for (int i = 0; i < 8; i++) {
        int gr = rowBase + ty * 8 + i;
        float c[8];
        unpack2(acc[i][0], c[0], c[1]);
        unpack2(acc[i][1], c[2], c[3]);
        unpack2(acc[i][2], c[4], c[5]);
        unpack2(acc[i][3], c[6], c[7]);
        if (gr < NN) {
            *(float4*)(g_h + (size_t)gr * DD + tx * 8)     = make_float4(c[0], c[1], c[2], c[3]);
            *(float4*)(g_h + (size_t)gr * DD + tx * 8 + 4) = make_float4(c[4], c[5], c[6], c[7]);
        }
        float ssum = 0.f, dsum = 0.f;
#pragma unroll
        for (int j = 0; j < 8; j++) {
            ssum = fmaf(c[j], av[j], ssum);
            dsum = fmaf(c[j], dv[j], dsum);
        }
        ssum += __shfl_xor_sync(0xFFFFFFFFu, ssum, 1);
        dsum += __shfl_xor_sync(0xFFFFFFFFu, dsum, 1);
        if (((tx & 1) == 0) && gr < NN) {
            g_as[gr * HH + head] = ssum;
            g_ad[gr * HH + head] = dsum;
        }
    }
}

// ---------------- aggregation: one warp per dst node, unrolled x2 ---------------
__global__ __launch_bounds__(256) void k_agg(float* __restrict__ out,
                                             float* __restrict__ alphaOut,
                                             const float* __restrict__ bias) {
    int warpId = (blockIdx.x * blockDim.x + threadIdx.x) >> 5;
    int lane = threadIdx.x & 31;
    if (warpId >= NN) return;
    const int n = warpId;
    const int beg = g_off[n], end = g_off[n + 1];

    float ad = (lane < HH) ? g_ad[n * HH + lane] : 0.f;
    float denom = 0.f;
    float acc0 = 0.f, acc1 = 0.f, acc2 = 0.f, acc3 = 0.f;
    const int hsel = lane >> 4;          // 0 or 1

    int p = beg;
    for (; p + 1 < end; p += 2) {
        int s0 = g_srcList[p];
        int s1 = g_srcList[p + 1];
        float ex0 = 0.f, ex1 = 0.f;
        if (lane < HH) {
            float l0 = g_as[s0 * HH + lane] + ad;
            float l1 = g_as[s1 * HH + lane] + ad;
            l0 = l0 > 0.f ? l0 : 0.2f * l0;
            l1 = l1 > 0.f ? l1 : 0.2f * l1;
            ex0 = __expf(l0);
            ex1 = __expf(l1);
            denom += ex0 + ex1;
        }
        float e00 = __shfl_sync(0xFFFFFFFFu, ex0, hsel);
        float e01 = __shfl_sync(0xFFFFFFFFu, ex0, 2 + hsel);
        float e02 = __shfl_sync(0xFFFFFFFFu, ex0, 4 + hsel);
        float e03 = __shfl_sync(0xFFFFFFFFu, ex0, 6 + hsel);
        float e10 = __shfl_sync(0xFFFFFFFFu, ex1, hsel);
        float e11 = __shfl_sync(0xFFFFFFFFu, ex1, 2 + hsel);
        float e12 = __shfl_sync(0xFFFFFFFFu, ex1, 4 + hsel);
        float e13 = __shfl_sync(0xFFFFFFFFu, ex1, 6 + hsel);
        const float* h0 = g_h + (size_t)s0 * DD;
        const float* h1 = g_h + (size_t)s1 * DD;
        float v00 = h0[lane],      v01 = h0[lane + 32];
        float v02 = h0[lane + 64], v03 = h0[lane + 96];
        float v10 = h1[lane],      v11 = h1[lane + 32];
        float v12 = h1[lane + 64], v13 = h1[lane + 96];
        acc0 = fmaf(e00, v00, acc0); acc1 = fmaf(e01, v01, acc1);
        acc2 = fmaf(e02, v02, acc2); acc3 = fmaf(e03, v03, acc3);
        acc0 = fmaf(e10, v10, acc0); acc1 = fmaf(e11, v11, acc1);
        acc2 = fmaf(e12, v12, acc2); acc3 = fmaf(e13, v13, acc3);
    }
    for (; p < end; p++) {
        int src = g_srcList[p];
        float ex = 0.f;
        if (lane < HH) {
            float l = g_as[src * HH + lane] + ad;
            l = l > 0.f ? l : 0.2f * l;
            ex = __expf(l);
            denom += ex;
        }
        float e0 = __shfl_sync(0xFFFFFFFFu, ex, hsel);
        float e1 = __shfl_sync(0xFFFFFFFFu, ex, 2 + hsel);
        float e2 = __shfl_sync(0xFFFFFFFFu, ex, 4 + hsel);
        float e3 = __shfl_sync(0xFFFFFFFFu, ex, 6 + hsel);
        const float* hp = g_h + (size_t)src * DD;
        acc0 = fmaf(e0, hp[lane],      acc0);
        acc1 = fmaf(e1, hp[lane + 32], acc1);
        acc2 = fmaf(e2, hp[lane + 64], acc2);
        acc3 = fmaf(e3, hp[lane + 96], acc3);
    }

    float dinv = (lane < HH) ? 1.f / (denom + 1e-16f) : 0.f;
    float d0 = __shfl_sync(0xFFFFFFFFu, dinv, hsel);
    float d1 = __shfl_sync(0xFFFFFFFFu, dinv, 2 + hsel);
    float d2 = __shfl_sync(0xFFFFFFFFu, dinv, 4 + hsel);
    float d3 = __shfl_sync(0xFFFFFFFFu, dinv, 6 + hsel);

    float* op = out + (size_t)n * DD;
    op[lane]      = acc0 * d0 + bias[lane];
    op[lane + 32] = acc1 * d1 + bias[lane + 32];
    op[lane + 64] = acc2 * d2 + bias[lane + 64];
    op[lane + 96] = acc3 * d3 + bias[lane + 96];

    if (alphaOut) {
        for (int q = beg; q < end; q++) {
            if (lane < HH) {
                int src = g_srcList[q];
                int eid = g_eidList[q];
                float l = g_as[src * HH + lane] + ad;
                l = l > 0.f ? l : 0.2f * l;
                alphaOut[(size_t)eid * HH + lane] = __expf(l) * dinv;
            }
        }
    }
}

// ---------------- optional ei output section -----------------------------------
__global__ void k_ei_f32(const void* __restrict__ ei, float* __restrict__ o) {
    int tid = blockIdx.x * blockDim.x + threadIdx.x;
    if (tid >= 2 * ETOT) return;
    int row = tid / ETOT;
    int i = tid - row * ETOT;
    long long v;
    if (i < EE) {
        v = g_is64 ? ((const long long*)ei)[(size_t)row * EE + i]
                   : (long long)((const int*)ei)[(size_t)row * EE + i];
    } else {
        v = (long long)(i - EE);
    }
    o[tid] = (float)v;
}

__global__ void k_ei_i64(const void* __restrict__ ei, long long* __restrict__ o) {
    int tid = blockIdx.x * blockDim.x + threadIdx.x;
    if (tid >= 2 * ETOT) return;
    int row = tid / ETOT;
    int i = tid - row * ETOT;
    long long v;
    if (i < EE) {
        v = g_is64 ? ((const long long*)ei)[(size_t)row * EE + i]
                   : (long long)((const int*)ei)[(size_t)row * EE + i];
    } else {
        v = (long long)(i - EE);
    }
    o[tid] = v;
}

// ---------------- launch --------------------------------------------------------
extern "C" void kernel_launch(void* const* d_in, const int* in_sizes, int n_in,
                              void* d_out, int out_size) {
    const float* x       = (const float*)d_in[0];
    const void*  ei      = d_in[1];
    const float* W       = (const float*)d_in[2];
    const float* att_src = (const float*)d_in[3];
    const float* att_dst = (const float*)d_in[4];
    const float* bias    = (const float*)d_in[5];
    float* out = (float*)d_out;

    const int OUTN = NN * DD;        // 12,800,000
    const int EIN  = 2 * ETOT;       //  1,800,000
    const int ALPH = ETOT * HH;      //  7,200,000

    float* alphaOut = nullptr;
    int    eiMode   = 0;             // 0 none, 1 float32, 2 int64
    if (out_size == OUTN + ALPH) {
        alphaOut = out + OUTN;
    } else if (out_size == OUTN + EIN + ALPH) {
        eiMode = 1;
        alphaOut = out + OUTN + EIN;
    } else if (out_size == OUTN + 2 * EIN + ALPH) {
        eiMode = 2;
        alphaOut = out + OUTN + 2 * EIN;
    }

    k_detect<<<1, 32>>>(ei);
    k_cnt_init<<<NB, 256>>>();
    k_hist<<<(EE + 255) / 256, 256>>>(ei);
    k_gemm<<<(NN + 127) / 128, 256>>>(x, W, att_src, att_dst);   // slot 4: profiled
    k_scan1<<<NB, 256>>>();
    k_scan2<<<1, 512>>>();
    k_scan3<<<NB, 256>>>();
    k_fill<<<(ETOT + 255) / 256, 256>>>(ei);
    k_agg<<<(NN * 32 + 255) / 256, 256>>>(out, alphaOut, bias);
    if (eiMode == 1) {
        k_ei_f32<<<(2 * ETOT + 255) / 256, 256>>>(ei, out + OUTN);
    } else if (eiMode == 2) {
        k_ei_i64<<<(2 * ETOT + 255) / 256, 256>>>(ei, (long long*)(out + OUTN));
    }
}

// round 16
// speedup vs baseline: 1.2391x; 1.2391x over previous
#include <cuda_runtime.h>
#include <cuda_bf16.h>

// GATConv (PyG default, add self-loops), fp32.  N=100000, D=128, H=8, C=16,
// E=800000, Etot=900000.
//
// R16: GEMM moved to tf32 mma.sync.m16n8k8 tensor cores (FFMA2 floor was
// ~45us; tensor floor ~15us). cvt.rna.tf32.f32 rounding on fragments keeps
// rel_err ~3e-5 (raw truncation would bias ~1e-3). Fused attn epilogue via
// quad shfl reduction. Rest of pipeline unchanged.

#define NN 100000
#define DD 128
#define HH 8
#define CC 16
#define EE 800000
#define ETOT 900000          // EE + NN
#define NB  ((NN + 255) / 256)   // 391 scan blocks

// ---------------- device scratch ----------------------------------------------
__device__ float g_h[NN * DD];          // 51.2 MB
__device__ float g_as[NN * HH];
__device__ float g_ad[NN * HH];
__device__ int   g_cnt[NN];
__device__ int   g_loc[NN];
__device__ int   g_bsum[NB];
__device__ int   g_off[NN + 1];
__device__ int   g_cur[NN];
__device__ int   g_srcList[ETOT];
__device__ int   g_eidList[ETOT];
__device__ int   g_is64;

// ---------------- dtype detect (parallel) ---------------------------------------
__global__ void k_detect(const void* __restrict__ ei) {
    int lane = threadIdx.x;
    const long long* p64 = (const long long*)ei;
    bool ok = true;
#pragma unroll
    for (int i = 0; i < 8; i++) {
        long long v = p64[lane + i * 32];
        if (v < 0 || v >= NN) ok = false;
    }
    unsigned m = __ballot_sync(0xFFFFFFFFu, ok);
    if (lane == 0) g_is64 = (m == 0xFFFFFFFFu) ? 1 : 0;
}

// ---------------- edge decode (dtype-aware) ------------------------------------
__device__ __forceinline__ bool edge_src_dst(const void* __restrict__ ei, int e,
                                             int& src, int& dst) {
    if (e >= EE) { src = dst = e - EE; return true; }   // self-loop
    if (g_is64) {
        src = (int)((const long long*)ei)[e];
        dst = (int)((const long long*)ei)[EE + e];
    } else {
        src = ((const int*)ei)[e];
        dst = ((const int*)ei)[EE + e];
    }
    return (unsigned)src < NN && (unsigned)dst < NN;
}

// ---------------- CSR build -----------------------------------------------------
__global__ void k_cnt_init() {
    int i = blockIdx.x * blockDim.x + threadIdx.x;
    if (i < NN) g_cnt[i] = 1;
}

__global__ void k_hist(const void* __restrict__ ei) {
    int e = blockIdx.x * blockDim.x + threadIdx.x;
    if (e >= EE) return;
    int src, dst;
    if (!edge_src_dst(ei, e, src, dst)) return;
    atomicAdd(&g_cnt[dst], 1);
}

__global__ void k_scan1() {
    __shared__ int s[256];
    int t = threadIdx.x;
    int i = blockIdx.x * 256 + t;
    int v = (i < NN) ? g_cnt[i] : 0;
    s[t] = v;
    __syncthreads();
#pragma unroll
    for (int d = 1; d < 256; d <<= 1) {
        int add = (t >= d) ? s[t - d] : 0;
        __syncthreads();
        s[t] += add;
        __syncthreads();
    }
    if (i < NN) g_loc[i] = s[t] - v;
    if (t == 255) g_bsum[blockIdx.x] = s[255];
}

__global__ void k_scan2() {
    __shared__ int s[512];
    int t = threadIdx.x;
    int v = (t < NB) ? g_bsum[t] : 0;
    s[t] = v;
    __syncthreads();
#pragma unroll
    for (int d = 1; d < 512; d <<= 1) {
        int add = (t >= d) ? s[t - d] : 0;
        __syncthreads();
        s[t] += add;
        __syncthreads();
    }
    if (t < NB) g_bsum[t] = s[t] - v;
}

__global__ void k_scan3() {
    int i = blockIdx.x * blockDim.x + threadIdx.x;
    if (i < NN) {
        int o = g_loc[i] + g_bsum[i >> 8];
        g_off[i] = o;
        g_cur[i] = o;
    }
    if (i == 0) g_off[NN] = ETOT;
}

__global__ void k_fill(const void* __restrict__ ei) {
    int e = blockIdx.x * blockDim.x + threadIdx.x;
    if (e >= ETOT) return;
    int src, dst;
    if (!edge_src_dst(ei, e, src, dst)) return;
    int pos = atomicAdd(&g_cur[dst], 1);
    g_srcList[pos] = src;
    g_eidList[pos] = e;
}

// ---------------- cp.async helpers ----------------------------------------------
__device__ __forceinline__ void cp16(void* smem_dst, const void* gsrc, int bytes) {
    unsigned int d = (unsigned int)__cvta_generic_to_shared(smem_dst);
    asm volatile("cp.async.ca.shared.global [%0], [%1], 16, %2;"
                 :: "r"(d), "l"(gsrc), "r"(bytes));
}
__device__ __forceinline__ void cp_commit() {
    asm volatile("cp.async.commit_group;");
}
template <int Ngroups>
__device__ __forceinline__ void cp_wait() {
    asm volatile("cp.async.wait_group %0;" :: "n"(Ngroups));
}

// ---------------- tf32 helpers --------------------------------------------------
__device__ __forceinline__ unsigned tf32r(float f) {
    unsigned u;
    asm("cvt.rna.tf32.f32 %0, %1;" : "=r"(u) : "f"(f));
    return u;
}

__device__ __forceinline__ void mma_tf32(float* c, const unsigned* a,
                                         unsigned b0, unsigned b1) {
    asm volatile(
        "mma.sync.aligned.m16n8k8.row.col.f32.tf32.tf32.f32 "
        "{%0,%1,%2,%3}, {%4,%5,%6,%7}, {%8,%9}, {%0,%1,%2,%3};"
        : "+f"(c[0]), "+f"(c[1]), "+f"(c[2]), "+f"(c[3])
        : "r"(a[0]), "r"(a[1]), "r"(a[2]), "r"(a[3]), "r"(b0), "r"(b1));
}

// ---------------- GEMM: h = x @ W (tf32 tensor cores), fused attn ---------------
// Block tile 128x128, 256 threads = 8 warps arranged 4(M) x 2(N).
// Warp tile m32n64: 2 m-tiles x 8 n-tiles of m16n8k8.
// KC=16 cp.async double buffer. Xs pad 20 (bank 4g+t), Ws pad 136 (bank 8t+g).
#define KC 16
#define XPAD 20
#define WPAD 136

__global__ __launch_bounds__(256) void k_gemm(const float* __restrict__ x,
                                              const float* __restrict__ W,
                                              const float* __restrict__ att_src,
                                              const float* __restrict__ att_dst) {
    __shared__ float Xs[2][128][XPAD];   // 20.5 KB
    __shared__ float Ws[2][KC][WPAD];    // 17.4 KB
    const int tid = threadIdx.x;
    const int warp = tid >> 5;
    const int lane = tid & 31;
    const int g = lane >> 2;         // group id 0..7
    const int t = lane & 3;          // thread-in-group 0..3
    const int wm = (warp >> 1) * 32; // warp M offset
    const int wn = (warp & 1) * 64;  // warp N offset
    const int rowBase = blockIdx.x * 128;

    float c[2][8][4];
#pragma unroll
    for (int mt = 0; mt < 2; mt++)
#pragma unroll
        for (int nt = 0; nt < 8; nt++)
#pragma unroll
            for (int q = 0; q < 4; q++) c[mt][nt][q] = 0.f;

    auto stage = [&](int k0, int buf) {
#pragma unroll
        for (int i = tid; i < 512; i += 256) {
            int r = i >> 2;
            int k4 = i & 3;
            int gr = rowBase + r;
            cp16(&Xs[buf][r][k4 * 4],
                 x + (size_t)(gr < NN ? gr : 0) * DD + k0 + k4 * 4,
                 gr < NN ? 16 : 0);
        }
#pragma unroll
        for (int i = tid; i < 512; i += 256) {
            int kk = i >> 5;
            int c4 = i & 31;
            cp16(&Ws[buf][kk][c4 * 4], W + (size_t)(k0 + kk) * DD + c4 * 4, 16);
        }
        cp_commit();
    };

    stage(0, 0);

#pragma unroll
    for (int it = 0; it < 8; it++) {
        if (it < 7) stage((it + 1) * KC, (it + 1) & 1);
        if (it < 7) cp_wait<1>(); else cp_wait<0>();
        __syncthreads();
        const int b = it & 1;
#pragma unroll
        for (int ks = 0; ks < 2; ks++) {          // two k8 steps per chunk
            const int kb = ks * 8;
            unsigned A[2][4];
#pragma unroll
            for (int mt = 0; mt < 2; mt++) {
                const int r0 = wm + 16 * mt + g;
                A[mt][0] = tf32r(Xs[b][r0][kb + t]);
                A[mt][1] = tf32r(Xs[b][r0 + 8][kb + t]);
                A[mt][2] = tf32r(Xs[b][r0][kb + t + 4]);
                A[mt][3] = tf32r(Xs[b][r0 + 8][kb + t + 4]);
            }
#pragma unroll
            for (int nt = 0; nt < 8; nt++) {
                unsigned B0 = tf32r(Ws[b][kb + t][wn + 8 * nt + g]);
                unsigned B1 = tf32r(Ws[b][kb + t + 4][wn + 8 * nt + g]);
                mma_tf32(c[0][nt], A[0], B0, B1);
                mma_tf32(c[1][nt], A[1], B0, B1);
            }
        }
        __syncthreads();
    }

    // attn vectors for this thread's 16 columns
    float av[8][2], dv[8][2];
#pragma unroll
    for (int nt = 0; nt < 8; nt++) {
        int col = wn + 8 * nt + 2 * t;
        av[nt][0] = att_src[col];     av[nt][1] = att_src[col + 1];
        dv[nt][0] = att_dst[col];     dv[nt][1] = att_dst[col + 1];
    }

#pragma unroll
    for (int mt = 0; mt < 2; mt++) {
#pragma unroll
        for (int half = 0; half < 2; half++) {
            int r = rowBase + wm + 16 * mt + 8 * half + g;
            bool ok = r < NN;
            float hs[4] = {0.f, 0.f, 0.f, 0.f};
            float hd[4] = {0.f, 0.f, 0.f, 0.f};
#pragma unroll
            for (int nt = 0; nt < 8; nt++) {
                float cA = half ? c[mt][nt][2] : c[mt][nt][0];
                float cB = half ? c[mt][nt][3] : c[mt][nt][1];
                if (ok) {
                    float2 v = make_float2(cA, cB);
                    *(float2*)(g_h + (size_t)r * DD + wn + 8 * nt + 2 * t) = v;
                }
                int q = nt >> 1;
                hs[q] = fmaf(cA, av[nt][0], fmaf(cB, av[nt][1], hs[q]));
                hd[q] = fmaf(cA, dv[nt][0], fmaf(cB, dv[nt][1], hd[q]));
            }
#pragma unroll
            for (int q = 0; q < 4; q++) {
                float ss = hs[q], dd = hd[q];
                ss += __shfl_xor_sync(0xFFFFFFFFu, ss, 1);
                ss += __shfl_xor_sync(0xFFFFFFFFu, ss, 2);
                dd += __shfl_xor_sync(0xFFFFFFFFu, dd, 1);
                dd += __shfl_xor_sync(0xFFFFFFFFu, dd, 2);
                if (t == 0 && ok) {
                    int head = (wn >> 4) + q;
                    g_as[r * HH + head] = ss;
                    g_ad[r * HH + head] = dd;
                }
            }
        }
    }
}

// ---------------- aggregation: one warp per dst node, unrolled x2 ---------------
__global__ __launch_bounds__(256) void k_agg(float* __restrict__ out,
                                             float* __restrict__ alphaOut,
                                             const float* __restrict__ bias) {
    int warpId = (blockIdx.x * blockDim.x + threadIdx.x) >> 5;
    int lane = threadIdx.x & 31;
    if (warpId >= NN) return;
    const int n = warpId;
    const int beg = g_off[n], end = g_off[n + 1];

    float ad = (lane < HH) ? g_ad[n * HH + lane] : 0.f;
    float denom = 0.f;
    float acc0 = 0.f, acc1 = 0.f, acc2 = 0.f, acc3 = 0.f;
    const int hsel = lane >> 4;          // 0 or 1

    int p = beg;
    for (; p + 1 < end; p += 2) {
        int s0 = g_srcList[p];
        int s1 = g_srcList[p + 1];
        float ex0 = 0.f, ex1 = 0.f;
        if (lane < HH) {
            float l0 = g_as[s0 * HH + lane] + ad;
            float l1 = g_as[s1 * HH + lane] + ad;
            l0 = l0 > 0.f ? l0 : 0.2f * l0;
            l1 = l1 > 0.f ? l1 : 0.2f * l1;
            ex0 = __expf(l0);
            ex1 = __expf(l1);
            denom += ex0 + ex1;
        }
        float e00 = __shfl_sync(0xFFFFFFFFu, ex0, hsel);
        float e01 = __shfl_sync(0xFFFFFFFFu, ex0, 2 + hsel);
        float e02 = __shfl_sync(0xFFFFFFFFu, ex0, 4 + hsel);
        float e03 = __shfl_sync(0xFFFFFFFFu, ex0, 6 + hsel);
        float e10 = __shfl_sync(0xFFFFFFFFu, ex1, hsel);
        float e11 = __shfl_sync(0xFFFFFFFFu, ex1, 2 + hsel);
        float e12 = __shfl_sync(0xFFFFFFFFu, ex1, 4 + hsel);
        float e13 = __shfl_sync(0xFFFFFFFFu, ex1, 6 + hsel);
        const float* h0 = g_h + (size_t)s0 * DD;
        const float* h1 = g_h + (size_t)s1 * DD;
        float v00 = h0[lane],      v01 = h0[lane + 32];
        float v02 = h0[lane + 64], v03 = h0[lane + 96];
        float v10 = h1[lane],      v11 = h1[lane + 32];
        float v12 = h1[lane + 64], v13 = h1[lane + 96];
        acc0 = fmaf(e00, v00, acc0); acc1 = fmaf(e01, v01, acc1);
        acc2 = fmaf(e02, v02, acc2); acc3 = fmaf(e03, v03, acc3);
        acc0 = fmaf(e10, v10, acc0); acc1 = fmaf(e11, v11, acc1);
        acc2 = fmaf(e12, v12, acc2); acc3 = fmaf(e13, v13, acc3);
    }
    for (; p < end; p++) {
        int src = g_srcList[p];
        float ex = 0.f;
        if (lane < HH) {
            float l = g_as[src * HH + lane] + ad;
            l = l > 0.f ? l : 0.2f * l;
            ex = __expf(l);
            denom += ex;
        }
        float e0 = __shfl_sync(0xFFFFFFFFu, ex, hsel);
        float e1 = __shfl_sync(0xFFFFFFFFu, ex, 2 + hsel);
        float e2 = __shfl_sync(0xFFFFFFFFu, ex, 4 + hsel);
        float e3 = __shfl_sync(0xFFFFFFFFu, ex, 6 + hsel);
        const float* hp = g_h + (size_t)src * DD;
        acc0 = fmaf(e0, hp[lane],      acc0);
        acc1 = fmaf(e1, hp[lane + 32], acc1);
        acc2 = fmaf(e2, hp[lane + 64], acc2);
        acc3 = fmaf(e3, hp[lane + 96], acc3);
    }

    float dinv = (lane < HH) ? 1.f / (denom + 1e-16f) : 0.f;
    float d0 = __shfl_sync(0xFFFFFFFFu, dinv, hsel);
    float d1 = __shfl_sync(0xFFFFFFFFu, dinv, 2 + hsel);
    float d2 = __shfl_sync(0xFFFFFFFFu, dinv, 4 + hsel);
    float d3 = __shfl_sync(0xFFFFFFFFu, dinv, 6 + hsel);

    float* op = out + (size_t)n * DD;
    op[lane]      = acc0 * d0 + bias[lane];
    op[lane + 32] = acc1 * d1 + bias[lane + 32];
    op[lane + 64] = acc2 * d2 + bias[lane + 64];
    op[lane + 96] = acc3 * d3 + bias[lane + 96];

    if (alphaOut) {
        for (int q = beg; q < end; q++) {
            if (lane < HH) {
                int src = g_srcList[q];
                int eid = g_eidList[q];
                float l = g_as[src * HH + lane] + ad;
                l = l > 0.f ? l : 0.2f * l;
                alphaOut[(size_t)eid * HH + lane] = __expf(l) * dinv;
            }
        }
    }
}

// ---------------- optional ei output section -----------------------------------
__global__ void k_ei_f32(const void* __restrict__ ei, float* __restrict__ o) {
    int tid = blockIdx.x * blockDim.x + threadIdx.x;
    if (tid >= 2 * ETOT) return;
    int row = tid / ETOT;
    int i = tid - row * ETOT;
    long long v;
    if (i < EE) {
        v = g_is64 ? ((const long long*)ei)[(size_t)row * EE + i]
                   : (long long)((const int*)ei)[(size_t)row * EE + i];
    } else {
        v = (long long)(i - EE);
    }
    o[tid] = (float)v;
}

__global__ void k_ei_i64(const void* __restrict__ ei, long long* __restrict__ o) {
    int tid = blockIdx.x * blockDim.x + threadIdx.x;
    if (tid >= 2 * ETOT) return;
    int row = tid / ETOT;
    int i = tid - row * ETOT;
    long long v;
    if (i < EE) {
        v = g_is64 ? ((const long long*)ei)[(size_t)row * EE + i]
                   : (long long)((const int*)ei)[(size_t)row * EE + i];
    } else {
        v = (long long)(i - EE);
    }
    o[tid] = v;
}

// ---------------- launch --------------------------------------------------------
extern "C" void kernel_launch(void* const* d_in, const int* in_sizes, int n_in,
                              void* d_out, int out_size) {
    const float* x       = (const float*)d_in[0];
    const void*  ei      = d_in[1];
    const float* W       = (const float*)d_in[2];
    const float* att_src = (const float*)d_in[3];
    const float* att_dst = (const float*)d_in[4];
    const float* bias    = (const float*)d_in[5];
    float* out = (float*)d_out;

    const int OUTN = NN * DD;        // 12,800,000
    const int EIN  = 2 * ETOT;       //  1,800,000
    const int ALPH = ETOT * HH;      //  7,200,000

    float* alphaOut = nullptr;
    int    eiMode   = 0;             // 0 none, 1 float32, 2 int64
    if (out_size == OUTN + ALPH) {
        alphaOut = out + OUTN;
    } else if (out_size == OUTN + EIN + ALPH) {
        eiMode = 1;
        alphaOut = out + OUTN + EIN;
    } else if (out_size == OUTN + 2 * EIN + ALPH) {
        eiMode = 2;
        alphaOut = out + OUTN + 2 * EIN;
    }

    k_detect<<<1, 32>>>(ei);
    k_cnt_init<<<NB, 256>>>();
    k_hist<<<(EE + 255) / 256, 256>>>(ei);
    k_gemm<<<(NN + 127) / 128, 256>>>(x, W, att_src, att_dst);   // slot 4: profiled
    k_scan1<<<NB, 256>>>();
    k_scan2<<<1, 512>>>();
    k_scan3<<<NB, 256>>>();
    k_fill<<<(ETOT + 255) / 256, 256>>>(ei);
    k_agg<<<(NN * 32 + 255) / 256, 256>>>(out, alphaOut, bias);
    if (eiMode == 1) {
        k_ei_f32<<<(2 * ETOT + 255) / 256, 256>>>(ei, out + OUTN);
    } else if (eiMode == 2) {
        k_ei_i64<<<(2 * ETOT + 255) / 256, 256>>>(ei, (long long*)(out + OUTN));
    }
}

// round 17
// speedup vs baseline: 1.4658x; 1.1829x over previous
#include <cuda_runtime.h>
#include <cuda_bf16.h>

// GATConv (PyG default, add self-loops), fp32.  N=100000, D=128, H=8, C=16,
// E=800000, Etot=900000.
//
// R17: k_agg reworked to float4 lanes (1 LDG.128 + 1 shfl + 4 FMA per edge,
// was 4 loads + 4 shfl); alpha computed by a new edge-parallel k_alpha with
// coalesced writes (k_agg stores g_dinv); k_fill no longer stores eidList.
// GEMM stays tf32 mma.sync (R16: 38us, tensor=28%).

#define NN 100000
#define DD 128
#define HH 8
#define CC 16
#define EE 800000
#define ETOT 900000          // EE + NN
#define NB  ((NN + 255) / 256)   // 391 scan blocks

// ---------------- device scratch ----------------------------------------------
__device__ float g_h[NN * DD];          // 51.2 MB
__device__ float g_as[NN * HH];
__device__ float g_ad[NN * HH];
__device__ float g_dinv[NN * HH];
__device__ int   g_cnt[NN];
__device__ int   g_loc[NN];
__device__ int   g_bsum[NB];
__device__ int   g_off[NN + 1];
__device__ int   g_cur[NN];
__device__ int   g_srcList[ETOT];
__device__ int   g_is64;

// ---------------- dtype detect (parallel) ---------------------------------------
__global__ void k_detect(const void* __restrict__ ei) {
    int lane = threadIdx.x;
    const long long* p64 = (const long long*)ei;
    bool ok = true;
#pragma unroll
    for (int i = 0; i < 8; i++) {
        long long v = p64[lane + i * 32];
        if (v < 0 || v >= NN) ok = false;
    }
    unsigned m = __ballot_sync(0xFFFFFFFFu, ok);
    if (lane == 0) g_is64 = (m == 0xFFFFFFFFu) ? 1 : 0;
}

// ---------------- edge decode (dtype-aware) ------------------------------------
__device__ __forceinline__ bool edge_src_dst(const void* __restrict__ ei, int e,
                                             int& src, int& dst) {
    if (e >= EE) { src = dst = e - EE; return true; }   // self-loop
    if (g_is64) {
        src = (int)((const long long*)ei)[e];
        dst = (int)((const long long*)ei)[EE + e];
    } else {
        src = ((const int*)ei)[e];
        dst = ((const int*)ei)[EE + e];
    }
    return (unsigned)src < NN && (unsigned)dst < NN;
}

// ---------------- CSR build -----------------------------------------------------
__global__ void k_cnt_init() {
    int i = blockIdx.x * blockDim.x + threadIdx.x;
    if (i < NN) g_cnt[i] = 1;
}

__global__ void k_hist(const void* __restrict__ ei) {
    int e = blockIdx.x * blockDim.x + threadIdx.x;
    if (e >= EE) return;
    int src, dst;
    if (!edge_src_dst(ei, e, src, dst)) return;
    atomicAdd(&g_cnt[dst], 1);
}

__global__ void k_scan1() {
    __shared__ int s[256];
    int t = threadIdx.x;
    int i = blockIdx.x * 256 + t;
    int v = (i < NN) ? g_cnt[i] : 0;
    s[t] = v;
    __syncthreads();
#pragma unroll
    for (int d = 1; d < 256; d <<= 1) {
        int add = (t >= d) ? s[t - d] : 0;
        __syncthreads();
        s[t] += add;
        __syncthreads();
    }
    if (i < NN) g_loc[i] = s[t] - v;
    if (t == 255) g_bsum[blockIdx.x] = s[255];
}

__global__ void k_scan2() {
    __shared__ int s[512];
    int t = threadIdx.x;
    int v = (t < NB) ? g_bsum[t] : 0;
    s[t] = v;
    __syncthreads();
#pragma unroll
    for (int d = 1; d < 512; d <<= 1) {
        int add = (t >= d) ? s[t - d] : 0;
        __syncthreads();
        s[t] += add;
        __syncthreads();
    }
    if (t < NB) g_bsum[t] = s[t] - v;
}

__global__ void k_scan3() {
    int i = blockIdx.x * blockDim.x + threadIdx.x;
    if (i < NN) {
        int o = g_loc[i] + g_bsum[i >> 8];
        g_off[i] = o;
        g_cur[i] = o;
    }
    if (i == 0) g_off[NN] = ETOT;
}

__global__ void k_fill(const void* __restrict__ ei) {
    int e = blockIdx.x * blockDim.x + threadIdx.x;
    if (e >= ETOT) return;
    int src, dst;
    if (!edge_src_dst(ei, e, src, dst)) return;
    int pos = atomicAdd(&g_cur[dst], 1);
    g_srcList[pos] = src;
}

// ---------------- cp.async helpers ----------------------------------------------
__device__ __forceinline__ void cp16(void* smem_dst, const void* gsrc, int bytes) {
    unsigned int d = (unsigned int)__cvta_generic_to_shared(smem_dst);
    asm volatile("cp.async.ca.shared.global [%0], [%1], 16, %2;"
                 :: "r"(d), "l"(gsrc), "r"(bytes));
}
__device__ __forceinline__ void cp_commit() {
    asm volatile("cp.async.commit_group;");
}
template <int Ngroups>
__device__ __forceinline__ void cp_wait() {
    asm volatile("cp.async.wait_group %0;" :: "n"(Ngroups));
}

// ---------------- tf32 helpers --------------------------------------------------
__device__ __forceinline__ unsigned tf32r(float f) {
    unsigned u;
    asm("cvt.rna.tf32.f32 %0, %1;" : "=r"(u) : "f"(f));
    return u;
}

__device__ __forceinline__ void mma_tf32(float* c, const unsigned* a,
                                         unsigned b0, unsigned b1) {
    asm volatile(
        "mma.sync.aligned.m16n8k8.row.col.f32.tf32.tf32.f32 "
        "{%0,%1,%2,%3}, {%4,%5,%6,%7}, {%8,%9}, {%0,%1,%2,%3};"
        : "+f"(c[0]), "+f"(c[1]), "+f"(c[2]), "+f"(c[3])
        : "r"(a[0]), "r"(a[1]), "r"(a[2]), "r"(a[3]), "r"(b0), "r"(b1));
}

// ---------------- GEMM: h = x @ W (tf32 tensor cores), fused attn ---------------
#define KC 16
#define XPAD 20
#define WPAD 136

__global__ __launch_bounds__(256) void k_gemm(const float* __restrict__ x,
                                              const float* __restrict__ W,
                                              const float* __restrict__ att_src,
                                              const float* __restrict__ att_dst) {
    __shared__ float Xs[2][128][XPAD];
    __shared__ float Ws[2][KC][WPAD];
    const int tid = threadIdx.x;
    const int warp = tid >> 5;
    const int lane = tid & 31;
    const int g = lane >> 2;
    const int t = lane & 3;
    const int wm = (warp >> 1) * 32;
    const int wn = (warp & 1) * 64;
    const int rowBase = blockIdx.x * 128;

    float c[2][8][4];
#pragma unroll
    for (int mt = 0; mt < 2; mt++)
#pragma unroll
        for (int nt = 0; nt < 8; nt++)
#pragma unroll
            for (int q = 0; q < 4; q++) c[mt][nt][q] = 0.f;

    auto stage = [&](int k0, int buf) {
#pragma unroll
        for (int i = tid; i < 512; i += 256) {
            int r = i >> 2;
            int k4 = i & 3;
            int gr = rowBase + r;
            cp16(&Xs[buf][r][k4 * 4],
                 x + (size_t)(gr < NN ? gr : 0) * DD + k0 + k4 * 4,
                 gr < NN ? 16 : 0);
        }
#pragma unroll
        for (int i = tid; i < 512; i += 256) {
            int kk = i >> 5;
            int c4 = i & 31;
            cp16(&Ws[buf][kk][c4 * 4], W + (size_t)(k0 + kk) * DD + c4 * 4, 16);
        }
        cp_commit();
    };

    stage(0, 0);

#pragma unroll
    for (int it = 0; it < 8; it++) {
        if (it < 7) stage((it + 1) * KC, (it + 1) & 1);
        if (it < 7) cp_wait<1>(); else cp_wait<0>();
        __syncthreads();
        const int b = it & 1;
#pragma unroll
        for (int ks = 0; ks < 2; ks++) {
            const int kb = ks * 8;
            unsigned A[2][4];
#pragma unroll
            for (int mt = 0; mt < 2; mt++) {
                const int r0 = wm + 16 * mt + g;
                A[mt][0] = tf32r(Xs[b][r0][kb + t]);
                A[mt][1] = tf32r(Xs[b][r0 + 8][kb + t]);
                A[mt][2] = tf32r(Xs[b][r0][kb + t + 4]);
                A[mt][3] = tf32r(Xs[b][r0 + 8][kb + t + 4]);
            }
#pragma unroll
            for (int nt = 0; nt < 8; nt++) {
                unsigned B0 = tf32r(Ws[b][kb + t][wn + 8 * nt + g]);
                unsigned B1 = tf32r(Ws[b][kb + t + 4][wn + 8 * nt + g]);
                mma_tf32(c[0][nt], A[0], B0, B1);
                mma_tf32(c[1][nt], A[1], B0, B1);
            }
        }
        __syncthreads();
    }

    float av[8][2], dv[8][2];
#pragma unroll
    for (int nt = 0; nt < 8; nt++) {
        int col = wn + 8 * nt + 2 * t;
        av[nt][0] = att_src[col];     av[nt][1] = att_src[col + 1];
        dv[nt][0] = att_dst[col];     dv[nt][1] = att_dst[col + 1];
    }

#pragma unroll
    for (int mt = 0; mt < 2; mt++) {
#pragma unroll
        for (int half = 0; half < 2; half++) {
            int r = rowBase + wm + 16 * mt + 8 * half + g;
            bool ok = r < NN;
            float hs[4] = {0.f, 0.f, 0.f, 0.f};
            float hd[4] = {0.f, 0.f, 0.f, 0.f};
#pragma unroll
            for (int nt = 0; nt < 8; nt++) {
                float cA = half ? c[mt][nt][2] : c[mt][nt][0];
                float cB = half ? c[mt][nt][3] : c[mt][nt][1];
                if (ok) {
                    float2 v = make_float2(cA, cB);
                    *(float2*)(g_h + (size_t)r * DD + wn + 8 * nt + 2 * t) = v;
                }
                int q = nt >> 1;
                hs[q] = fmaf(cA, av[nt][0], fmaf(cB, av[nt][1], hs[q]));
                hd[q] = fmaf(cA, dv[nt][0], fmaf(cB, dv[nt][1], hd[q]));
            }
#pragma unroll
            for (int q = 0; q < 4; q++) {
                float ss = hs[q], dd = hd[q];
                ss += __shfl_xor_sync(0xFFFFFFFFu, ss, 1);
                ss += __shfl_xor_sync(0xFFFFFFFFu, ss, 2);
                dd += __shfl_xor_sync(0xFFFFFFFFu, dd, 1);
                dd += __shfl_xor_sync(0xFFFFFFFFu, dd, 2);
                if (t == 0 && ok) {
                    int head = (wn >> 4) + q;
                    g_as[r * HH + head] = ss;
                    g_ad[r * HH + head] = dd;
                }
            }
        }
    }
}

// ---------------- aggregation: one warp per node, float4 lanes ------------------
// Lane l owns channels [4l, 4l+4) -> head l>>2. 1 LDG.128 + 1 shfl + 4 FMA/edge.
__global__ __launch_bounds__(256) void k_agg(float* __restrict__ out,
                                             const float* __restrict__ bias) {
    int warpId = (blockIdx.x * blockDim.x + threadIdx.x) >> 5;
    int lane = threadIdx.x & 31;
    if (warpId >= NN) return;
    const int n = warpId;
    const int beg = g_off[n], end = g_off[n + 1];
    const int hq = lane >> 2;            // head for this lane's float4

    float ad = (lane < HH) ? g_ad[n * HH + lane] : 0.f;
    float denom = 0.f;
    float4 acc = make_float4(0.f, 0.f, 0.f, 0.f);

    int p = beg;
    for (; p + 1 < end; p += 2) {
        int s0 = g_srcList[p];
        int s1 = g_srcList[p + 1];
        float ex0 = 0.f, ex1 = 0.f;
        if (lane < HH) {
            float l0 = g_as[s0 * HH + lane] + ad;
            float l1 = g_as[s1 * HH + lane] + ad;
            l0 = l0 > 0.f ? l0 : 0.2f * l0;
            l1 = l1 > 0.f ? l1 : 0.2f * l1;
            ex0 = __expf(l0);
            ex1 = __expf(l1);
            denom += ex0 + ex1;
        }
        float e0 = __shfl_sync(0xFFFFFFFFu, ex0, hq);
        float e1 = __shfl_sync(0xFFFFFFFFu, ex1, hq);
        float4 v0 = ((const float4*)(g_h + (size_t)s0 * DD))[lane];
        float4 v1 = ((const float4*)(g_h + (size_t)s1 * DD))[lane];
        acc.x = fmaf(e0, v0.x, acc.x); acc.y = fmaf(e0, v0.y, acc.y);
        acc.z = fmaf(e0, v0.z, acc.z); acc.w = fmaf(e0, v0.w, acc.w);
        acc.x = fmaf(e1, v1.x, acc.x); acc.y = fmaf(e1, v1.y, acc.y);
        acc.z = fmaf(e1, v1.z, acc.z); acc.w = fmaf(e1, v1.w, acc.w);
    }
    for (; p < end; p++) {
        int src = g_srcList[p];
        float ex = 0.f;
        if (lane < HH) {
            float l = g_as[src * HH + lane] + ad;
            l = l > 0.f ? l : 0.2f * l;
            ex = __expf(l);
            denom += ex;
        }
        float e = __shfl_sync(0xFFFFFFFFu, ex, hq);
        float4 v = ((const float4*)(g_h + (size_t)src * DD))[lane];
        acc.x = fmaf(e, v.x, acc.x); acc.y = fmaf(e, v.y, acc.y);
        acc.z = fmaf(e, v.z, acc.z); acc.w = fmaf(e, v.w, acc.w);
    }

    float dinv = 0.f;
    if (lane < HH) {
        dinv = 1.f / (denom + 1e-16f);
        g_dinv[n * HH + lane] = dinv;
    }
    float d = __shfl_sync(0xFFFFFFFFu, dinv, hq);

    float4 b = ((const float4*)bias)[lane];
    float4 o;
    o.x = acc.x * d + b.x;
    o.y = acc.y * d + b.y;
    o.z = acc.z * d + b.z;
    o.w = acc.w * d + b.w;
    ((float4*)(out + (size_t)n * DD))[lane] = o;
}

// ---------------- edge-parallel alpha (coalesced writes) ------------------------
__global__ void k_alpha(const void* __restrict__ ei, float* __restrict__ alphaOut) {
    int tid = blockIdx.x * blockDim.x + threadIdx.x;
    if (tid >= ETOT * HH) return;
    int e = tid >> 3;
    int h = tid & 7;
    int src, dst;
    if (!edge_src_dst(ei, e, src, dst)) { alphaOut[tid] = 0.f; return; }
    float l = g_as[src * HH + h] + g_ad[dst * HH + h];
    l = l > 0.f ? l : 0.2f * l;
    alphaOut[tid] = __expf(l) * g_dinv[dst * HH + h];
}

// ---------------- optional ei output section -----------------------------------
__global__ void k_ei_f32(const void* __restrict__ ei, float* __restrict__ o) {
    int tid = blockIdx.x * blockDim.x + threadIdx.x;
    if (tid >= 2 * ETOT) return;
    int row = tid / ETOT;
    int i = tid - row * ETOT;
    long long v;
    if (i < EE) {
        v = g_is64 ? ((const long long*)ei)[(size_t)row * EE + i]
                   : (long long)((const int*)ei)[(size_t)row * EE + i];
    } else {
        v = (long long)(i - EE);
    }
    o[tid] = (float)v;
}

__global__ void k_ei_i64(const void* __restrict__ ei, long long* __restrict__ o) {
    int tid = blockIdx.x * blockDim.x + threadIdx.x;
    if (tid >= 2 * ETOT) return;
    int row = tid / ETOT;
    int i = tid - row * ETOT;
    long long v;
    if (i < EE) {
        v = g_is64 ? ((const long long*)ei)[(size_t)row * EE + i]
                   : (long long)((const int*)ei)[(size_t)row * EE + i];
    } else {
        v = (long long)(i - EE);
    }
    o[tid] = v;
}

// ---------------- launch --------------------------------------------------------
extern "C" void kernel_launch(void* const* d_in, const int* in_sizes, int n_in,
                              void* d_out, int out_size) {
    const float* x       = (const float*)d_in[0];
    const void*  ei      = d_in[1];
    const float* W       = (const float*)d_in[2];
    const float* att_src = (const float*)d_in[3];
    const float* att_dst = (const float*)d_in[4];
    const float* bias    = (const float*)d_in[5];
    float* out = (float*)d_out;

    const int OUTN = NN * DD;        // 12,800,000
    const int EIN  = 2 * ETOT;       //  1,800,000
    const int ALPH = ETOT * HH;      //  7,200,000

    float* alphaOut = nullptr;
    int    eiMode   = 0;             // 0 none, 1 float32, 2 int64
    if (out_size == OUTN + ALPH) {
        alphaOut = out + OUTN;
    } else if (out_size == OUTN + EIN + ALPH) {
        eiMode = 1;
        alphaOut = out + OUTN + EIN;
    } else if (out_size == OUTN + 2 * EIN + ALPH) {
        eiMode = 2;
        alphaOut = out + OUTN + 2 * EIN;
    }

    k_detect<<<1, 32>>>(ei);
    k_cnt_init<<<NB, 256>>>();
    k_hist<<<(EE + 255) / 256, 256>>>(ei);
    k_gemm<<<(NN + 127) / 128, 256>>>(x, W, att_src, att_dst);   // slot 4: profiled
    k_scan1<<<NB, 256>>>();
    k_scan2<<<1, 512>>>();
    k_scan3<<<NB, 256>>>();
    k_fill<<<(ETOT + 255) / 256, 256>>>(ei);
    k_agg<<<(NN * 32 + 255) / 256, 256>>>(out, bias);
    if (alphaOut) {
        k_alpha<<<(ETOT * HH + 255) / 256, 256>>>(ei, alphaOut);
    }
    if (eiMode == 1) {
        k_ei_f32<<<(2 * ETOT + 255) / 256, 256>>>(ei, out + OUTN);
    } else if (eiMode == 2) {
        k_ei_i64<<<(2 * ETOT + 255) / 256, 256>>>(ei, (long long*)(out + OUTN));
    }
}